// round 11
// baseline (speedup 1.0000x reference)
#include <cuda_runtime.h>
#include <cuda_fp16.h>
#include <math_constants.h>

#define Nn 50000
#define Ee 800000
#define Hh 64
#define EDd 32
#define Ll 3
#define Gg 256
#define OUTd 32
#define NB 49   // ceil(Nn/1024)

// ---------------- static device scratch ----------------
__device__ float  d_QS[Nn * 128];    // q(0..63) | skip(64..127), fp32
__device__ __half d_KV[Nn * 128];    // k(0..63) | v(64..127), fp16
__device__ float  d_H[Nn * 64];      // node features
__device__ int    d_CNT[Nn];         // zeroed by k_scan1 for next replay
__device__ int    d_CUR[Nn];
__device__ int    d_OFF[Nn + 1];
__device__ int    d_BT[64];          // scan block totals
__device__ unsigned d_EPK[Ee];       // CSR slots: src | (attr<<16)
__device__ float  d_ET[Ll * 640];    // per-layer edge-type tables (10 types x 64)
__device__ unsigned d_GKEY[Gg];
__device__ float  d_GATE[Nn];
__device__ float  d_Y[Nn * OUTd];

// ---------------- helpers ----------------
__device__ __forceinline__ unsigned fkey(float f) {
    unsigned u = __float_as_uint(f);
    return (u & 0x80000000u) ? ~u : (u | 0x80000000u);
}
__device__ __forceinline__ float fdecode(unsigned k) {
    return (k & 0x80000000u) ? __uint_as_float(k & 0x7fffffffu) : __uint_as_float(~k);
}

// ---------------- prep: embed + hist + etab ----------------
__global__ void k_prep(const int* __restrict__ x, const float* __restrict__ node_emb,
                       const int* __restrict__ dst,
                       const float* __restrict__ edge_emb, const float* __restrict__ We) {
    int i = blockIdx.x * blockDim.x + threadIdx.x;
    if (i < Nn * 64) {
        int n = i >> 6, c = i & 63;
        d_H[i] = node_emb[x[n] * 64 + c];
    }
    if (i < Ee) atomicAdd(&d_CNT[dst[i]], 1);
    if (i < Ll * 640) {
        int l = i / 640, t = i % 640;
        int ty = t >> 6, c = t & 63;
        const float* W = We + l * (EDd * 64);
        float s = 0.f;
        #pragma unroll
        for (int j = 0; j < EDd; j++) s += edge_emb[ty * EDd + j] * W[j * 64 + c];
        d_ET[i] = s;
    }
    if (i < Gg) d_GKEY[i] = 0u;
}

// ---------------- CSR scan (self-cleaning) ----------------
__global__ void k_scan1() {
    __shared__ int wsum[32];
    int t = threadIdx.x, b = blockIdx.x;
    int i = b * 1024 + t;
    int v = (i < Nn) ? d_CNT[i] : 0;
    int lane = t & 31, w = t >> 5;
    int x = v;
    #pragma unroll
    for (int o = 1; o < 32; o <<= 1) {
        int y = __shfl_up_sync(0xffffffffu, x, o);
        if (lane >= o) x += y;
    }
    if (lane == 31) wsum[w] = x;
    __syncthreads();
    if (w == 0) {
        int s = wsum[lane];
        #pragma unroll
        for (int o = 1; o < 32; o <<= 1) {
            int y = __shfl_up_sync(0xffffffffu, s, o);
            if (lane >= o) s += y;
        }
        wsum[lane] = s;
    }
    __syncthreads();
    int excl = x - v + (w ? wsum[w - 1] : 0);
    if (i < Nn) {
        d_OFF[i] = excl;
        d_CNT[i] = 0;
        d_CUR[i] = 0;
    }
    if (t == 1023) d_BT[b] = excl + v;
}

// merged scan2+scan3: each block redundantly prefixes the 49 block totals
__global__ void k_scan3() {
    __shared__ int sBT[NB];
    __shared__ int tot;
    if (threadIdx.x == 0) {
        int s = 0;
        for (int b = 0; b < NB; b++) { sBT[b] = s; s += d_BT[b]; }
        tot = s;
    }
    __syncthreads();
    int i = blockIdx.x * blockDim.x + threadIdx.x;
    if (i < Nn) d_OFF[i] += sBT[i >> 10];
    if (i == 0) d_OFF[Nn] = tot;
}

__global__ void k_scatter(const int* __restrict__ src, const int* __restrict__ dst,
                          const int* __restrict__ attr) {
    int e = blockIdx.x * blockDim.x + threadIdx.x;
    if (e >= Ee) return;
    int d = dst[e];
    int p = atomicAdd(&d_CUR[d], 1);
    d_EPK[d_OFF[d] + p] = (unsigned)src[e] | ((unsigned)attr[e] << 16);
}

// ---------------- tensor-core q,k,v,skip GEMM (HMMA m16n8k16, fp16 in / fp32 acc) ----
#define HS_STR 72
#define WT_STR 72
__global__ void k_gemm(const float* __restrict__ Wq, const float* __restrict__ Wk,
                       const float* __restrict__ Wv, const float* __restrict__ Ws,
                       const float* __restrict__ bq, const float* __restrict__ bk,
                       const float* __restrict__ bv, const float* __restrict__ bs, int l) {
    extern __shared__ char smemc[];
    __half* hs = (__half*)smemc;                       // [32][HS_STR]
    __half* Wt = (__half*)(smemc + 32 * HS_STR * 2);   // [256][WT_STR]
    float*  bc = (float*)(smemc + 32 * HS_STR * 2 + 256 * WT_STR * 2);  // [256]
    int t = threadIdx.x;

    for (int m = 0; m < 4; m++) {
        const float* W = (m == 0 ? Wq : m == 1 ? Wk : m == 2 ? Wv : Ws) + l * 4096;
        for (int i = t; i < 4096; i += 256) {
            int kk = i >> 6, cc = i & 63;
            Wt[(m * 64 + cc) * WT_STR + kk] = __float2half(W[kk * 64 + cc]);
        }
    }
    {
        const float* B = (t < 64) ? bq : (t < 128) ? bk : (t < 192) ? bv : bs;
        bc[t] = B[l * 64 + (t & 63)];
    }
    int node0 = blockIdx.x * 32;
    for (int i = t; i < 32 * 64; i += 256) {
        int n = i >> 6, kk = i & 63;
        int gn = node0 + n;
        hs[n * HS_STR + kk] = __float2half(gn < Nn ? __ldg(&d_H[gn * 64 + kk]) : 0.f);
    }
    __syncthreads();

    int lane = t & 31, w = t >> 5;
    int g = lane >> 2, t4 = lane & 3;
    int rbase = (w & 1) * 16;
    int mtx = w >> 1;
    const __half* wrow0 = Wt + (mtx * 64) * WT_STR;

    float c0[8], c1[8], c2[8], c3[8];
    #pragma unroll
    for (int nt = 0; nt < 8; nt++) { c0[nt] = c1[nt] = c2[nt] = c3[nt] = 0.f; }

    #pragma unroll
    for (int ks = 0; ks < 4; ks++) {
        int k0 = ks * 16;
        unsigned ra0 = *(const unsigned*)&hs[(rbase + g) * HS_STR + k0 + 2 * t4];
        unsigned ra1 = *(const unsigned*)&hs[(rbase + g + 8) * HS_STR + k0 + 2 * t4];
        unsigned ra2 = *(const unsigned*)&hs[(rbase + g) * HS_STR + k0 + 2 * t4 + 8];
        unsigned ra3 = *(const unsigned*)&hs[(rbase + g + 8) * HS_STR + k0 + 2 * t4 + 8];
        #pragma unroll
        for (int nt = 0; nt < 8; nt++) {
            const __half* wr = wrow0 + (nt * 8 + g) * WT_STR + k0;
            unsigned rb0 = *(const unsigned*)&wr[2 * t4];
            unsigned rb1 = *(const unsigned*)&wr[2 * t4 + 8];
            asm volatile(
                "mma.sync.aligned.m16n8k16.row.col.f32.f16.f16.f32 "
                "{%0,%1,%2,%3}, {%4,%5,%6,%7}, {%8,%9}, {%0,%1,%2,%3};"
                : "+f"(c0[nt]), "+f"(c1[nt]), "+f"(c2[nt]), "+f"(c3[nt])
                : "r"(ra0), "r"(ra1), "r"(ra2), "r"(ra3), "r"(rb0), "r"(rb1));
        }
    }

    int gn0 = node0 + rbase + g;
    int gn1 = gn0 + 8;
    #pragma unroll
    for (int nt = 0; nt < 8; nt++) {
        int col = nt * 8 + 2 * t4;
        float b0 = bc[mtx * 64 + col], b1 = bc[mtx * 64 + col + 1];
        float v00 = c0[nt] + b0, v01 = c1[nt] + b1;
        float v10 = c2[nt] + b0, v11 = c3[nt] + b1;
        if (mtx == 0) {
            if (gn0 < Nn) *(float2*)&d_QS[gn0 * 128 + col] = make_float2(v00, v01);
            if (gn1 < Nn) *(float2*)&d_QS[gn1 * 128 + col] = make_float2(v10, v11);
        } else if (mtx == 3) {
            if (gn0 < Nn) *(float2*)&d_QS[gn0 * 128 + 64 + col] = make_float2(v00, v01);
            if (gn1 < Nn) *(float2*)&d_QS[gn1 * 128 + 64 + col] = make_float2(v10, v11);
        } else {
            int off = (mtx == 1) ? 0 : 64;
            if (gn0 < Nn) *(__half2*)&d_KV[gn0 * 128 + off + col] = __floats2half2_rn(v00, v01);
            if (gn1 < Nn) *(__half2*)&d_KV[gn1 * 128 + off + col] = __floats2half2_rn(v10, v11);
        }
    }
}
#define GEMM_SMEM (32 * HS_STR * 2 + 256 * WT_STR * 2 + 256 * 4)

// ---------------- edge kernel: no-max softmax + factored edge-type term ----------------
// warp per node; 4 groups of 8 lanes, group owns one edge at a time.
// alpha = (q.k + q.e_ty)*s ; out = (Sum p*v + Sum_ty P_ty*e_ty)/Sum p + skip
__global__ void k_edge(int l) {
    __shared__ float et[640];
    __shared__ float sQE[8 * 10];    // per-warp q.e_ty (pre-scaled)
    __shared__ float sPT[8 * 40];    // per-warp per-group per-type p sums
    for (int i = threadIdx.x; i < 640; i += blockDim.x) et[i] = d_ET[l * 640 + i];
    __syncthreads();

    int n = (blockIdx.x * blockDim.x + threadIdx.x) >> 5;
    int lane = threadIdx.x & 31;
    int w = (threadIdx.x >> 5);
    if (n >= Nn) return;
    int g = lane >> 3, r = lane & 7;
    unsigned gmask = 0xffu << (g * 8);
    int s0 = d_OFF[n], s1 = d_OFF[n + 1];
    int co = r * 8;

    if (s0 == s1) {          // isolated node: h = relu(skip)
        if (g == 0) {
            float4 sk0 = *(const float4*)&d_QS[n * 128 + 64 + co];
            float4 sk1 = *(const float4*)&d_QS[n * 128 + 64 + co + 4];
            float4 o0, o1;
            o0.x = fmaxf(sk0.x, 0.f); o0.y = fmaxf(sk0.y, 0.f);
            o0.z = fmaxf(sk0.z, 0.f); o0.w = fmaxf(sk0.w, 0.f);
            o1.x = fmaxf(sk1.x, 0.f); o1.y = fmaxf(sk1.y, 0.f);
            o1.z = fmaxf(sk1.z, 0.f); o1.w = fmaxf(sk1.w, 0.f);
            *(float4*)&d_H[n * 64 + co] = o0;
            *(float4*)&d_H[n * 64 + co + 4] = o1;
        }
        return;
    }

    float4 q0 = *(const float4*)&d_QS[n * 128 + co];
    float4 q1 = *(const float4*)&d_QS[n * 128 + co + 4];

    // prologue: qe[ty] = (q . e_ty) for the 10 types (group g covers ty = g, g+4, g+8)
    for (int ty = g; ty < 10; ty += 4) {
        const float* e = &et[ty * 64 + co];
        float s = q0.x * e[0] + q0.y * e[1] + q0.z * e[2] + q0.w * e[3]
                + q1.x * e[4] + q1.y * e[5] + q1.z * e[6] + q1.w * e[7];
        s += __shfl_xor_sync(gmask, s, 1);
        s += __shfl_xor_sync(gmask, s, 2);
        s += __shfl_xor_sync(gmask, s, 4);
        if (r == 0) sQE[w * 10 + ty] = s;
    }
    {   // zero per-type p sums
        int base = w * 40;
        if (lane < 20) { sPT[base + lane] = 0.f; sPT[base + lane + 20] = 0.f; }
    }
    __syncwarp();

    float ssum = 0.f;
    float a[8];
    #pragma unroll
    for (int c = 0; c < 8; c++) a[c] = 0.f;

    // 2-deep pipeline: pk two stages ahead, k/v one stage ahead
    int iA = s0 + g;
    bool vA = iA < s1;
    unsigned pkA = vA ? __ldg(&d_EPK[iA]) : 0u;
    int iB = iA + 4;
    bool vB = iB < s1;
    unsigned pkB = vB ? __ldg(&d_EPK[iB]) : 0u;
    uint4 kA, vvA;
    if (vA) {
        const uint4* b = (const uint4*)&d_KV[(pkA & 0xffffu) * 128 + co];
        kA = __ldg(b); vvA = __ldg(b + 8);   // +8 uint4 = +64 halfs (v block)
    }

    while (vA) {
        uint4 kB, vvB;
        if (vB) {
            const uint4* b = (const uint4*)&d_KV[(pkB & 0xffffu) * 128 + co];
            kB = __ldg(b); vvB = __ldg(b + 8);
        }
        int iC = iB + 4;
        bool vC = iC < s1;
        unsigned pkC = vC ? __ldg(&d_EPK[iC]) : 0u;

        int ty = pkA >> 16;
        float2 kx = __half22float2(*(__half2*)&kA.x);
        float2 ky = __half22float2(*(__half2*)&kA.y);
        float2 kz = __half22float2(*(__half2*)&kA.z);
        float2 kw = __half22float2(*(__half2*)&kA.w);
        float d = q0.x * kx.x + q0.y * kx.y + q0.z * ky.x + q0.w * ky.y
                + q1.x * kz.x + q1.y * kz.y + q1.z * kw.x + q1.w * kw.y;
        d += __shfl_xor_sync(gmask, d, 1);
        d += __shfl_xor_sync(gmask, d, 2);
        d += __shfl_xor_sync(gmask, d, 4);
        float p = __expf((d + sQE[w * 10 + ty]) * 0.125f);
        ssum += p;
        float2 vx = __half22float2(*(__half2*)&vvA.x);
        float2 vy = __half22float2(*(__half2*)&vvA.y);
        float2 vz = __half22float2(*(__half2*)&vvA.z);
        float2 vw = __half22float2(*(__half2*)&vvA.w);
        a[0] += p * vx.x; a[1] += p * vx.y;
        a[2] += p * vy.x; a[3] += p * vy.y;
        a[4] += p * vz.x; a[5] += p * vz.y;
        a[6] += p * vw.x; a[7] += p * vw.y;
        if (r == 0) sPT[w * 40 + g * 10 + ty] += p;

        pkA = pkB; vA = vB;
        kA = kB; vvA = vvB;
        pkB = pkC; vB = vC; iB = iC;
    }
    __syncwarp();

    // combine groups
    ssum += __shfl_xor_sync(0xffffffffu, ssum, 8);
    ssum += __shfl_xor_sync(0xffffffffu, ssum, 16);
    #pragma unroll
    for (int c = 0; c < 8; c++) {
        a[c] += __shfl_xor_sync(0xffffffffu, a[c], 8);
        a[c] += __shfl_xor_sync(0xffffffffu, a[c], 16);
    }

    if (g == 0) {
        int base = w * 40;
        #pragma unroll
        for (int ty = 0; ty < 10; ty++) {
            float pt = sPT[base + ty] + sPT[base + 10 + ty]
                     + sPT[base + 20 + ty] + sPT[base + 30 + ty];
            const float* e = &et[ty * 64 + co];
            a[0] += pt * e[0]; a[1] += pt * e[1];
            a[2] += pt * e[2]; a[3] += pt * e[3];
            a[4] += pt * e[4]; a[5] += pt * e[5];
            a[6] += pt * e[6]; a[7] += pt * e[7];
        }
        float inv = 1.f / ssum;
        float4 sk0 = *(const float4*)&d_QS[n * 128 + 64 + co];
        float4 sk1 = *(const float4*)&d_QS[n * 128 + 64 + co + 4];
        float4 o0, o1;
        o0.x = fmaxf(a[0] * inv + sk0.x, 0.f);
        o0.y = fmaxf(a[1] * inv + sk0.y, 0.f);
        o0.z = fmaxf(a[2] * inv + sk0.z, 0.f);
        o0.w = fmaxf(a[3] * inv + sk0.w, 0.f);
        o1.x = fmaxf(a[4] * inv + sk1.x, 0.f);
        o1.y = fmaxf(a[5] * inv + sk1.y, 0.f);
        o1.z = fmaxf(a[6] * inv + sk1.z, 0.f);
        o1.w = fmaxf(a[7] * inv + sk1.w, 0.f);
        *(float4*)&d_H[n * 64 + co] = o0;
        *(float4*)&d_H[n * 64 + co + 4] = o1;
    }
}

// ---------------- merged readout: y + gate + per-graph max ----------------
__global__ void k_outy(const float* __restrict__ out_W, const float* __restrict__ out_b,
                       const float* __restrict__ gW, const float* __restrict__ gb,
                       const int* __restrict__ batch) {
    __shared__ float Wm[64 * OUTd];
    __shared__ float gws[64];
    __shared__ float bb[OUTd];
    for (int i = threadIdx.x; i < 64 * OUTd; i += 256) Wm[i] = out_W[i];
    if (threadIdx.x < 64) gws[threadIdx.x] = gW[threadIdx.x];
    if (threadIdx.x < OUTd) bb[threadIdx.x] = out_b[threadIdx.x];
    __syncthreads();
    int n = blockIdx.x * 8 + (threadIdx.x >> 5);
    int c = threadIdx.x & 31;
    if (n >= Nn) return;
    float h0 = d_H[n * 64 + c];
    float h1 = d_H[n * 64 + 32 + c];
    float s = bb[c];
    #pragma unroll
    for (int kk = 0; kk < 32; kk++) {
        s += __shfl_sync(0xffffffffu, h0, kk) * Wm[kk * OUTd + c];
        s += __shfl_sync(0xffffffffu, h1, kk) * Wm[(32 + kk) * OUTd + c];
    }
    d_Y[n * OUTd + c] = s;
    float gv = h0 * gws[c] + h1 * gws[32 + c];
    #pragma unroll
    for (int o = 16; o; o >>= 1) gv += __shfl_xor_sync(0xffffffffu, gv, o);
    gv += gb[0];
    if (c == 0) {
        d_GATE[n] = gv;
        atomicMax(&d_GKEY[batch[n]], fkey(gv));
    }
}

// ---------------- segmented final readout: one block per graph, no atomics ----------------
__global__ void k_red(const int* __restrict__ batch, float* __restrict__ out) {
    int g = blockIdx.x;
    __shared__ int lohi[2];
    if (threadIdx.x == 0) {
        int lo = 0, hi = Nn;
        while (lo < hi) { int mid = (lo + hi) >> 1; if (batch[mid] < g) lo = mid + 1; else hi = mid; }
        lohi[0] = lo;
        int lo2 = lo, hi2 = Nn;
        while (lo2 < hi2) { int mid = (lo2 + hi2) >> 1; if (batch[mid] < g + 1) lo2 = mid + 1; else hi2 = mid; }
        lohi[1] = lo2;
    }
    __syncthreads();
    int n0 = lohi[0], n1 = lohi[1];
    float mx = fdecode(d_GKEY[g]);
    int c = threadIdx.x & 31;       // output column
    int nl = threadIdx.x >> 5;      // node lane 0..7
    float acc = 0.f, den = 0.f;
    for (int n = n0 + nl; n < n1; n += 8) {
        float p = __expf(d_GATE[n] - mx);
        acc += p * d_Y[n * OUTd + c];
        den += p;
    }
    __shared__ float sacc[8][33];
    __shared__ float sden[8];
    sacc[nl][c] = acc;
    if (c == 0) sden[nl] = den;
    __syncthreads();
    if (nl == 0) {
        float s = 0.f, dtot = 0.f;
        #pragma unroll
        for (int k = 0; k < 8; k++) { s += sacc[k][c]; dtot += sden[k]; }
        out[g * OUTd + c] = (dtot > 0.f) ? s / dtot : 0.f;
    }
}

// ---------------- launch ----------------
extern "C" void kernel_launch(void* const* d_in, const int* in_sizes, int n_in,
                              void* d_out, int out_size) {
    const int*   x        = (const int*)d_in[0];
    const int*   ei       = (const int*)d_in[1];
    const int*   ea       = (const int*)d_in[2];
    const int*   batch    = (const int*)d_in[3];
    const float* node_emb = (const float*)d_in[4];
    const float* edge_emb = (const float*)d_in[5];
    const float* Wq       = (const float*)d_in[6];
    const float* Wk       = (const float*)d_in[7];
    const float* Wv       = (const float*)d_in[8];
    const float* We       = (const float*)d_in[9];
    const float* Wskip    = (const float*)d_in[10];
    const float* bq       = (const float*)d_in[11];
    const float* bk       = (const float*)d_in[12];
    const float* bv       = (const float*)d_in[13];
    const float* bskip    = (const float*)d_in[14];
    const float* gate_W   = (const float*)d_in[15];
    const float* gate_b   = (const float*)d_in[16];
    const float* out_W    = (const float*)d_in[17];
    const float* out_b    = (const float*)d_in[18];
    float* out = (float*)d_out;

    const int* srcp = ei;
    const int* dstp = ei + Ee;

    static bool attr_set = false;
    if (!attr_set) {
        cudaFuncSetAttribute(k_gemm, cudaFuncAttributeMaxDynamicSharedMemorySize, GEMM_SMEM);
        attr_set = true;
    }

    k_prep<<<(Nn * 64 + 255) / 256, 256>>>(x, node_emb, dstp, edge_emb, We);
    k_scan1<<<NB, 1024>>>();
    k_scan3<<<(Nn + 255) / 256, 256>>>();
    k_scatter<<<(Ee + 255) / 256, 256>>>(srcp, dstp, ea);

    for (int l = 0; l < Ll; l++) {
        k_gemm<<<(Nn + 31) / 32, 256, GEMM_SMEM>>>(Wq, Wk, Wv, Wskip, bq, bk, bv, bskip, l);
        k_edge<<<(Nn * 32 + 255) / 256, 256>>>(l);
    }

    k_outy<<<(Nn + 7) / 8, 256>>>(out_W, out_b, gate_W, gate_b, batch);
    k_red<<<Gg, 256>>>(batch, out);
}

// round 13
// speedup vs baseline: 1.1268x; 1.1268x over previous
#include <cuda_runtime.h>
#include <cuda_fp16.h>
#include <math_constants.h>

#define Nn 50000
#define Ee 800000
#define Hh 64
#define EDd 32
#define Ll 3
#define Gg 256
#define OUTd 32
#define NB 49   // ceil(Nn/1024)

// ---------------- static device scratch ----------------
__device__ float  d_QS[Nn * 128];    // q(0..63) | skip(64..127), fp32
__device__ __half d_KV[Nn * 128];    // k(0..63) | v(64..127), fp16
__device__ float  d_H[Nn * 64];      // node features
__device__ int    d_CNT[Nn];         // zeroed by k_scan1 for next replay
__device__ int    d_CUR[Nn];
__device__ int    d_OFF[Nn + 1];
__device__ int    d_BT[64];          // scan block totals
__device__ unsigned d_EPK[Ee];       // CSR slots: src | (attr<<16)
__device__ float  d_ET[Ll * 640];    // per-layer edge-type tables (10 types x 64)
__device__ unsigned d_GKEY[Gg];
__device__ float  d_GATE[Nn];
__device__ float  d_Y[Nn * OUTd];

// ---------------- helpers ----------------
__device__ __forceinline__ unsigned fkey(float f) {
    unsigned u = __float_as_uint(f);
    return (u & 0x80000000u) ? ~u : (u | 0x80000000u);
}
__device__ __forceinline__ float fdecode(unsigned k) {
    return (k & 0x80000000u) ? __uint_as_float(k & 0x7fffffffu) : __uint_as_float(~k);
}

// ---------------- prep: embed + hist + etab ----------------
__global__ void k_prep(const int* __restrict__ x, const float* __restrict__ node_emb,
                       const int* __restrict__ dst,
                       const float* __restrict__ edge_emb, const float* __restrict__ We) {
    int i = blockIdx.x * blockDim.x + threadIdx.x;
    if (i < Nn * 64) {
        int n = i >> 6, c = i & 63;
        d_H[i] = node_emb[x[n] * 64 + c];
    }
    if (i < Ee) atomicAdd(&d_CNT[dst[i]], 1);
    if (i < Ll * 640) {
        int l = i / 640, t = i % 640;
        int ty = t >> 6, c = t & 63;
        const float* W = We + l * (EDd * 64);
        float s = 0.f;
        #pragma unroll
        for (int j = 0; j < EDd; j++) s += edge_emb[ty * EDd + j] * W[j * 64 + c];
        d_ET[i] = s;
    }
    if (i < Gg) d_GKEY[i] = 0u;
}

// ---------------- CSR scan (self-cleaning) ----------------
__global__ void k_scan1() {
    __shared__ int wsum[32];
    int t = threadIdx.x, b = blockIdx.x;
    int i = b * 1024 + t;
    int v = (i < Nn) ? d_CNT[i] : 0;
    int lane = t & 31, w = t >> 5;
    int x = v;
    #pragma unroll
    for (int o = 1; o < 32; o <<= 1) {
        int y = __shfl_up_sync(0xffffffffu, x, o);
        if (lane >= o) x += y;
    }
    if (lane == 31) wsum[w] = x;
    __syncthreads();
    if (w == 0) {
        int s = wsum[lane];
        #pragma unroll
        for (int o = 1; o < 32; o <<= 1) {
            int y = __shfl_up_sync(0xffffffffu, s, o);
            if (lane >= o) s += y;
        }
        wsum[lane] = s;
    }
    __syncthreads();
    int excl = x - v + (w ? wsum[w - 1] : 0);
    if (i < Nn) {
        d_OFF[i] = excl;
        d_CNT[i] = 0;
        d_CUR[i] = 0;
    }
    if (t == 1023) d_BT[b] = excl + v;
}

// merged scan2+scan3: each block redundantly prefixes the 49 block totals
__global__ void k_scan3() {
    __shared__ int sBT[NB];
    __shared__ int tot;
    if (threadIdx.x == 0) {
        int s = 0;
        for (int b = 0; b < NB; b++) { sBT[b] = s; s += d_BT[b]; }
        tot = s;
    }
    __syncthreads();
    int i = blockIdx.x * blockDim.x + threadIdx.x;
    if (i < Nn) d_OFF[i] += sBT[i >> 10];
    if (i == 0) d_OFF[Nn] = tot;
}

__global__ void k_scatter(const int* __restrict__ src, const int* __restrict__ dst,
                          const int* __restrict__ attr) {
    int e = blockIdx.x * blockDim.x + threadIdx.x;
    if (e >= Ee) return;
    int d = dst[e];
    int p = atomicAdd(&d_CUR[d], 1);
    d_EPK[d_OFF[d] + p] = (unsigned)src[e] | ((unsigned)attr[e] << 16);
}

// ---------------- tensor-core q,k,v,skip GEMM (HMMA m16n8k16, fp16 in / fp32 acc) ----
#define HS_STR 72
#define WT_STR 72
__global__ void k_gemm(const float* __restrict__ Wq, const float* __restrict__ Wk,
                       const float* __restrict__ Wv, const float* __restrict__ Ws,
                       const float* __restrict__ bq, const float* __restrict__ bk,
                       const float* __restrict__ bv, const float* __restrict__ bs, int l) {
    extern __shared__ char smemc[];
    __half* hs = (__half*)smemc;                       // [32][HS_STR]
    __half* Wt = (__half*)(smemc + 32 * HS_STR * 2);   // [256][WT_STR]
    float*  bc = (float*)(smemc + 32 * HS_STR * 2 + 256 * WT_STR * 2);  // [256]
    int t = threadIdx.x;

    for (int m = 0; m < 4; m++) {
        const float* W = (m == 0 ? Wq : m == 1 ? Wk : m == 2 ? Wv : Ws) + l * 4096;
        for (int i = t; i < 4096; i += 256) {
            int kk = i >> 6, cc = i & 63;
            Wt[(m * 64 + cc) * WT_STR + kk] = __float2half(W[kk * 64 + cc]);
        }
    }
    {
        const float* B = (t < 64) ? bq : (t < 128) ? bk : (t < 192) ? bv : bs;
        bc[t] = B[l * 64 + (t & 63)];
    }
    int node0 = blockIdx.x * 32;
    for (int i = t; i < 32 * 64; i += 256) {
        int n = i >> 6, kk = i & 63;
        int gn = node0 + n;
        hs[n * HS_STR + kk] = __float2half(gn < Nn ? __ldg(&d_H[gn * 64 + kk]) : 0.f);
    }
    __syncthreads();

    int lane = t & 31, w = t >> 5;
    int g = lane >> 2, t4 = lane & 3;
    int rbase = (w & 1) * 16;
    int mtx = w >> 1;
    const __half* wrow0 = Wt + (mtx * 64) * WT_STR;

    float c0[8], c1[8], c2[8], c3[8];
    #pragma unroll
    for (int nt = 0; nt < 8; nt++) { c0[nt] = c1[nt] = c2[nt] = c3[nt] = 0.f; }

    #pragma unroll
    for (int ks = 0; ks < 4; ks++) {
        int k0 = ks * 16;
        unsigned ra0 = *(const unsigned*)&hs[(rbase + g) * HS_STR + k0 + 2 * t4];
        unsigned ra1 = *(const unsigned*)&hs[(rbase + g + 8) * HS_STR + k0 + 2 * t4];
        unsigned ra2 = *(const unsigned*)&hs[(rbase + g) * HS_STR + k0 + 2 * t4 + 8];
        unsigned ra3 = *(const unsigned*)&hs[(rbase + g + 8) * HS_STR + k0 + 2 * t4 + 8];
        #pragma unroll
        for (int nt = 0; nt < 8; nt++) {
            const __half* wr = wrow0 + (nt * 8 + g) * WT_STR + k0;
            unsigned rb0 = *(const unsigned*)&wr[2 * t4];
            unsigned rb1 = *(const unsigned*)&wr[2 * t4 + 8];
            asm volatile(
                "mma.sync.aligned.m16n8k16.row.col.f32.f16.f16.f32 "
                "{%0,%1,%2,%3}, {%4,%5,%6,%7}, {%8,%9}, {%0,%1,%2,%3};"
                : "+f"(c0[nt]), "+f"(c1[nt]), "+f"(c2[nt]), "+f"(c3[nt])
                : "r"(ra0), "r"(ra1), "r"(ra2), "r"(ra3), "r"(rb0), "r"(rb1));
        }
    }

    int gn0 = node0 + rbase + g;
    int gn1 = gn0 + 8;
    #pragma unroll
    for (int nt = 0; nt < 8; nt++) {
        int col = nt * 8 + 2 * t4;
        float b0 = bc[mtx * 64 + col], b1 = bc[mtx * 64 + col + 1];
        float v00 = c0[nt] + b0, v01 = c1[nt] + b1;
        float v10 = c2[nt] + b0, v11 = c3[nt] + b1;
        if (mtx == 0) {
            if (gn0 < Nn) *(float2*)&d_QS[gn0 * 128 + col] = make_float2(v00, v01);
            if (gn1 < Nn) *(float2*)&d_QS[gn1 * 128 + col] = make_float2(v10, v11);
        } else if (mtx == 3) {
            if (gn0 < Nn) *(float2*)&d_QS[gn0 * 128 + 64 + col] = make_float2(v00, v01);
            if (gn1 < Nn) *(float2*)&d_QS[gn1 * 128 + 64 + col] = make_float2(v10, v11);
        } else {
            int off = (mtx == 1) ? 0 : 64;
            if (gn0 < Nn) *(__half2*)&d_KV[gn0 * 128 + off + col] = __floats2half2_rn(v00, v01);
            if (gn1 < Nn) *(__half2*)&d_KV[gn1 * 128 + off + col] = __floats2half2_rn(v10, v11);
        }
    }
}
#define GEMM_SMEM (32 * HS_STR * 2 + 256 * WT_STR * 2 + 256 * 4)

// ---------------- edge kernel: warp per node, no-max softmax (validated), in-loop et ----
__global__ void k_edge(int l) {
    __shared__ float et[640];
    for (int i = threadIdx.x; i < 640; i += blockDim.x) et[i] = d_ET[l * 640 + i];
    __syncthreads();

    int n = (blockIdx.x * blockDim.x + threadIdx.x) >> 5;
    int lane = threadIdx.x & 31;
    if (n >= Nn) return;
    int g = lane >> 3, r = lane & 7;
    unsigned gmask = 0xffu << (g * 8);
    int s0 = d_OFF[n], s1 = d_OFF[n + 1];
    int co = r * 8;

    if (s0 == s1) {          // isolated node: h = relu(skip)
        if (g == 0) {
            float4 sk0 = *(const float4*)&d_QS[n * 128 + 64 + co];
            float4 sk1 = *(const float4*)&d_QS[n * 128 + 64 + co + 4];
            float4 o0, o1;
            o0.x = fmaxf(sk0.x, 0.f); o0.y = fmaxf(sk0.y, 0.f);
            o0.z = fmaxf(sk0.z, 0.f); o0.w = fmaxf(sk0.w, 0.f);
            o1.x = fmaxf(sk1.x, 0.f); o1.y = fmaxf(sk1.y, 0.f);
            o1.z = fmaxf(sk1.z, 0.f); o1.w = fmaxf(sk1.w, 0.f);
            *(float4*)&d_H[n * 64 + co] = o0;
            *(float4*)&d_H[n * 64 + co + 4] = o1;
        }
        return;
    }

    float4 q0 = *(const float4*)&d_QS[n * 128 + co];
    float4 q1 = *(const float4*)&d_QS[n * 128 + co + 4];

    float ssum = 0.f;
    float a[8];
    #pragma unroll
    for (int c = 0; c < 8; c++) a[c] = 0.f;

    // 2-deep pipeline: pk two stages ahead, k/v one stage ahead
    int iA = s0 + g;
    bool vA = iA < s1;
    unsigned pkA = vA ? __ldg(&d_EPK[iA]) : 0u;
    int iB = iA + 4;
    bool vB = iB < s1;
    unsigned pkB = vB ? __ldg(&d_EPK[iB]) : 0u;
    uint4 kA, vvA;
    if (vA) {
        const uint4* b = (const uint4*)&d_KV[(pkA & 0xffffu) * 128 + co];
        kA = __ldg(b); vvA = __ldg(b + 8);   // +8 uint4 = +64 halfs (v block)
    }

    while (vA) {
        uint4 kB, vvB;
        if (vB) {
            const uint4* b = (const uint4*)&d_KV[(pkB & 0xffffu) * 128 + co];
            kB = __ldg(b); vvB = __ldg(b + 8);
        }
        int iC = iB + 4;
        bool vC = iC < s1;
        unsigned pkC = vC ? __ldg(&d_EPK[iC]) : 0u;

        int ty = pkA >> 16;
        float4 e0 = *(const float4*)&et[ty * 64 + co];
        float4 e1 = *(const float4*)&et[ty * 64 + co + 4];
        float2 kx = __half22float2(*(__half2*)&kA.x);
        float2 ky = __half22float2(*(__half2*)&kA.y);
        float2 kz = __half22float2(*(__half2*)&kA.z);
        float2 kw = __half22float2(*(__half2*)&kA.w);
        float d = q0.x * (kx.x + e0.x) + q0.y * (kx.y + e0.y)
                + q0.z * (ky.x + e0.z) + q0.w * (ky.y + e0.w)
                + q1.x * (kz.x + e1.x) + q1.y * (kz.y + e1.y)
                + q1.z * (kw.x + e1.z) + q1.w * (kw.y + e1.w);
        d += __shfl_xor_sync(gmask, d, 1);
        d += __shfl_xor_sync(gmask, d, 2);
        d += __shfl_xor_sync(gmask, d, 4);
        float p = __expf(d * 0.125f);        // no-max softmax (shift-invariant; validated R11)
        ssum += p;
        float2 vx = __half22float2(*(__half2*)&vvA.x);
        float2 vy = __half22float2(*(__half2*)&vvA.y);
        float2 vz = __half22float2(*(__half2*)&vvA.z);
        float2 vw = __half22float2(*(__half2*)&vvA.w);
        a[0] += p * (vx.x + e0.x);
        a[1] += p * (vx.y + e0.y);
        a[2] += p * (vy.x + e0.z);
        a[3] += p * (vy.y + e0.w);
        a[4] += p * (vz.x + e1.x);
        a[5] += p * (vz.y + e1.y);
        a[6] += p * (vw.x + e1.z);
        a[7] += p * (vw.y + e1.w);

        pkA = pkB; vA = vB;
        kA = kB; vvA = vvB;
        pkB = pkC; vB = vC; iB = iC;
    }

    // combine the 4 groups (plain sums; no max bookkeeping)
    ssum += __shfl_xor_sync(0xffffffffu, ssum, 8);
    ssum += __shfl_xor_sync(0xffffffffu, ssum, 16);
    #pragma unroll
    for (int c = 0; c < 8; c++) {
        a[c] += __shfl_xor_sync(0xffffffffu, a[c], 8);
        a[c] += __shfl_xor_sync(0xffffffffu, a[c], 16);
    }
    float inv = 1.f / ssum;

    if (g == 0) {
        float4 sk0 = *(const float4*)&d_QS[n * 128 + 64 + co];
        float4 sk1 = *(const float4*)&d_QS[n * 128 + 64 + co + 4];
        float4 o0, o1;
        o0.x = fmaxf(a[0] * inv + sk0.x, 0.f);
        o0.y = fmaxf(a[1] * inv + sk0.y, 0.f);
        o0.z = fmaxf(a[2] * inv + sk0.z, 0.f);
        o0.w = fmaxf(a[3] * inv + sk0.w, 0.f);
        o1.x = fmaxf(a[4] * inv + sk1.x, 0.f);
        o1.y = fmaxf(a[5] * inv + sk1.y, 0.f);
        o1.z = fmaxf(a[6] * inv + sk1.z, 0.f);
        o1.w = fmaxf(a[7] * inv + sk1.w, 0.f);
        *(float4*)&d_H[n * 64 + co] = o0;
        *(float4*)&d_H[n * 64 + co + 4] = o1;
    }
}

// ---------------- merged readout: y + gate + per-graph max ----------------
__global__ void k_outy(const float* __restrict__ out_W, const float* __restrict__ out_b,
                       const float* __restrict__ gW, const float* __restrict__ gb,
                       const int* __restrict__ batch) {
    __shared__ float Wm[64 * OUTd];
    __shared__ float gws[64];
    __shared__ float bb[OUTd];
    for (int i = threadIdx.x; i < 64 * OUTd; i += 256) Wm[i] = out_W[i];
    if (threadIdx.x < 64) gws[threadIdx.x] = gW[threadIdx.x];
    if (threadIdx.x < OUTd) bb[threadIdx.x] = out_b[threadIdx.x];
    __syncthreads();
    int n = blockIdx.x * 8 + (threadIdx.x >> 5);
    int c = threadIdx.x & 31;
    if (n >= Nn) return;
    float h0 = d_H[n * 64 + c];
    float h1 = d_H[n * 64 + 32 + c];
    float s = bb[c];
    #pragma unroll
    for (int kk = 0; kk < 32; kk++) {
        s += __shfl_sync(0xffffffffu, h0, kk) * Wm[kk * OUTd + c];
        s += __shfl_sync(0xffffffffu, h1, kk) * Wm[(32 + kk) * OUTd + c];
    }
    d_Y[n * OUTd + c] = s;
    float gv = h0 * gws[c] + h1 * gws[32 + c];
    #pragma unroll
    for (int o = 16; o; o >>= 1) gv += __shfl_xor_sync(0xffffffffu, gv, o);
    gv += gb[0];
    if (c == 0) {
        d_GATE[n] = gv;
        atomicMax(&d_GKEY[batch[n]], fkey(gv));
    }
}

// ---------------- segmented final readout: one block per graph, no atomics ----------------
__global__ void k_red(const int* __restrict__ batch, float* __restrict__ out) {
    int g = blockIdx.x;
    __shared__ int lohi[2];
    if (threadIdx.x == 0) {
        int lo = 0, hi = Nn;
        while (lo < hi) { int mid = (lo + hi) >> 1; if (batch[mid] < g) lo = mid + 1; else hi = mid; }
        lohi[0] = lo;
        int lo2 = lo, hi2 = Nn;
        while (lo2 < hi2) { int mid = (lo2 + hi2) >> 1; if (batch[mid] < g + 1) lo2 = mid + 1; else hi2 = mid; }
        lohi[1] = lo2;
    }
    __syncthreads();
    int n0 = lohi[0], n1 = lohi[1];
    float mx = fdecode(d_GKEY[g]);
    int c = threadIdx.x & 31;       // output column
    int nl = threadIdx.x >> 5;      // node lane 0..7
    float acc = 0.f, den = 0.f;
    for (int n = n0 + nl; n < n1; n += 8) {
        float p = __expf(d_GATE[n] - mx);
        acc += p * d_Y[n * OUTd + c];
        den += p;
    }
    __shared__ float sacc[8][33];
    __shared__ float sden[8];
    sacc[nl][c] = acc;
    if (c == 0) sden[nl] = den;
    __syncthreads();
    if (nl == 0) {
        float s = 0.f, dtot = 0.f;
        #pragma unroll
        for (int k = 0; k < 8; k++) { s += sacc[k][c]; dtot += sden[k]; }
        out[g * OUTd + c] = (dtot > 0.f) ? s / dtot : 0.f;
    }
}

// ---------------- launch ----------------
extern "C" void kernel_launch(void* const* d_in, const int* in_sizes, int n_in,
                              void* d_out, int out_size) {
    const int*   x        = (const int*)d_in[0];
    const int*   ei       = (const int*)d_in[1];
    const int*   ea       = (const int*)d_in[2];
    const int*   batch    = (const int*)d_in[3];
    const float* node_emb = (const float*)d_in[4];
    const float* edge_emb = (const float*)d_in[5];
    const float* Wq       = (const float*)d_in[6];
    const float* Wk       = (const float*)d_in[7];
    const float* Wv       = (const float*)d_in[8];
    const float* We       = (const float*)d_in[9];
    const float* Wskip    = (const float*)d_in[10];
    const float* bq       = (const float*)d_in[11];
    const float* bk       = (const float*)d_in[12];
    const float* bv       = (const float*)d_in[13];
    const float* bskip    = (const float*)d_in[14];
    const float* gate_W   = (const float*)d_in[15];
    const float* gate_b   = (const float*)d_in[16];
    const float* out_W    = (const float*)d_in[17];
    const float* out_b    = (const float*)d_in[18];
    float* out = (float*)d_out;

    const int* srcp = ei;
    const int* dstp = ei + Ee;

    static bool attr_set = false;
    if (!attr_set) {
        cudaFuncSetAttribute(k_gemm, cudaFuncAttributeMaxDynamicSharedMemorySize, GEMM_SMEM);
        attr_set = true;
    }

    k_prep<<<(Nn * 64 + 255) / 256, 256>>>(x, node_emb, dstp, edge_emb, We);
    k_scan1<<<NB, 1024>>>();
    k_scan3<<<(Nn + 255) / 256, 256>>>();
    k_scatter<<<(Ee + 255) / 256, 256>>>(srcp, dstp, ea);

    for (int l = 0; l < Ll; l++) {
        k_gemm<<<(Nn + 31) / 32, 256, GEMM_SMEM>>>(Wq, Wk, Wv, Wskip, bq, bk, bv, bskip, l);
        k_edge<<<(Nn * 32 + 255) / 256, 256>>>(l);
    }

    k_outy<<<(Nn + 7) / 8, 256>>>(out_W, out_b, gate_W, gate_b, batch);
    k_red<<<Gg, 256>>>(batch, out);
}